// round 3
// baseline (speedup 1.0000x reference)
#include <cuda_runtime.h>

#define NN 100000
#define MM 1000
#define KA 11    // A rank terms (k=1..11 of the 12; k=0 folded into B init)
#define KB 12    // B entries per m: [0]=c0*z0 (init), [1..11] pair with A[0..10]
#define TPB 128
#define VN 4     // n-values per thread (float4 store)
#define MC 200   // m-values per block
#define MT 5     // m-tiles (MC*MT = MM)

// Scratch (no cudaMalloc allowed)
__device__ float g_A[(size_t)KA * NN];  // SoA: g_A[k*NN + n]
__device__ float g_B[(size_t)MM * KB];  // AoS per m

typedef unsigned long long u64;

__device__ __forceinline__ u64 pack2(float lo, float hi) {
    u64 r; asm("mov.b64 %0, {%1,%2};" : "=l"(r) : "f"(lo), "f"(hi)); return r;
}
__device__ __forceinline__ void unpack2(u64 v, float& lo, float& hi) {
    asm("mov.b64 {%0,%1}, %2;" : "=f"(lo), "=f"(hi) : "l"(v));
}
__device__ __forceinline__ u64 fma2(u64 a, u64 b, u64 c) {
    u64 d; asm("fma.rn.f32x2 %0, %1, %2, %3;" : "=l"(d) : "l"(a), "l"(b), "l"(c)); return d;
}
__device__ __forceinline__ float fast_sin(float x)  { float r; asm("sin.approx.f32 %0, %1;"  : "=f"(r) : "f"(x)); return r; }
__device__ __forceinline__ float fast_cos(float x)  { float r; asm("cos.approx.f32 %0, %1;"  : "=f"(r) : "f"(x)); return r; }
__device__ __forceinline__ float fast_tanh(float x) { float r; asm("tanh.approx.f32 %0, %1;" : "=f"(r) : "f"(x)); return r; }

// Per-n features, 4 n per thread, SoA coalesced float4 stores.
// Also writes latent_spatial (N,2) output block.
__global__ void __launch_bounds__(TPB)
prep_A(const float* __restrict__ phi, const float* __restrict__ POD,
       const float* __restrict__ c, const float* __restrict__ omega,
       float* __restrict__ out_latent) {
    int n0 = (blockIdx.x * TPB + threadIdx.x) * 4;
    if (n0 >= NN) return;  // NN % 4 == 0

    float4 p0 = *(const float4*)(phi + n0);        // phi[0, n0..n0+3]
    float4 p1 = *(const float4*)(phi + NN + n0);   // phi[1, n0..n0+3]
    float4 qa = *(const float4*)(POD + 2 * n0);    // POD[n0..n0+1, :]
    float4 qb = *(const float4*)(POD + 2 * n0 + 4);

    float y0[4], y1[4];
    y0[0] = p0.x * qa.x;  y1[0] = p1.x * qa.y;
    y0[1] = p0.y * qa.z;  y1[1] = p1.y * qa.w;
    y0[2] = p0.z * qb.x;  y1[2] = p1.z * qb.y;
    y0[3] = p0.w * qb.z;  y1[3] = p1.w * qb.w;

    float c1 = c[1], c2 = c[2], c3 = c[3], c4 = c[4], c5 = c[5];
    float w0 = omega[0], w1 = omega[1], w2 = omega[2];
    float w3 = omega[3], w4 = omega[4], w5 = omega[5];

    float4 v;
#define STORE_COL(k, EXPR)                                                   \
    v.x = EXPR(0); v.y = EXPR(1); v.z = EXPR(2); v.w = EXPR(3);              \
    *(float4*)(g_A + (size_t)(k) * NN + n0) = v;

#define E0(j)  (c1 * y0[j])
#define E1(j)  (c2 * y1[j])
#define E2(j)  (c3 * y0[j] * y0[j])
#define E3(j)  (c4 * y0[j] * y1[j])
#define E4(j)  (c5 * y1[j] * y1[j])
#define E5(j)  fast_sin(w0 * y0[j])
#define E6(j)  fast_sin(w3 * y1[j])
#define E7(j)  fast_cos(w1 * y0[j])
#define E8(j)  fast_cos(w4 * y1[j])
#define E9(j)  fast_tanh(w2 * y0[j])
#define E10(j) fast_tanh(w5 * y1[j])
    STORE_COL(0, E0)  STORE_COL(1, E1)  STORE_COL(2, E2)  STORE_COL(3, E3)
    STORE_COL(4, E4)  STORE_COL(5, E5)  STORE_COL(6, E6)  STORE_COL(7, E7)
    STORE_COL(8, E8)  STORE_COL(9, E9)  STORE_COL(10, E10)

    float4 L0 = make_float4(y0[0], y1[0], y0[1], y1[1]);
    float4 L1 = make_float4(y0[2], y1[2], y0[3], y1[3]);
    *(float4*)(out_latent + 2 * n0)     = L0;
    *(float4*)(out_latent + 2 * n0 + 4) = L1;
}

// Per-m features; folds c0*z0 into slot 0; also copies z_values (6,M) to output.
__global__ void prep_B(const float* __restrict__ z, const float* __restrict__ zsin,
                       const float* __restrict__ zcos, const float* __restrict__ ztanh,
                       const float* __restrict__ sc, const float* __restrict__ cc,
                       const float* __restrict__ tc, const float* __restrict__ c,
                       float* __restrict__ out_z) {
    int m = blockIdx.x * blockDim.x + threadIdx.x;
    if (m >= MM) return;
    float* b = g_B + (size_t)m * KB;
    float z0 = z[m];
    b[0] = c[0] * z0;          // accumulator init term: c0 * z_values[0,m]
    out_z[m] = z0;
#pragma unroll
    for (int t = 1; t < 6; t++) {
        float v = z[t * MM + m];
        b[t] = v;
        out_z[t * MM + m] = v;
    }
    b[6]  = sc[0] * zsin[m];        b[7]  = sc[1] * zsin[MM + m];
    b[8]  = cc[0] * zcos[m];        b[9]  = cc[1] * zcos[MM + m];
    b[10] = tc[0] * ztanh[m];       b[11] = tc[1] * ztanh[MM + m];
}

// Rank-12 outer product with k=0 folded into init:
//   out[m*N + n] = B[m,0] + sum_{k=0..10} A[n,k] * B[m,k+1]
__global__ void __launch_bounds__(TPB)
main_kernel(float* __restrict__ out) {
    __shared__ __align__(16) u64 Bs[MC * KB];  // B duplicated into both f32x2 lanes

    int mBase = blockIdx.y * MC;
    for (int i = threadIdx.x; i < MC * KB; i += TPB) {
        float v = g_B[(size_t)mBase * KB + i];
        Bs[i] = pack2(v, v);
    }
    __syncthreads();

    int n0 = (blockIdx.x * TPB + threadIdx.x) * VN;
    if (n0 >= NN) return;   // NN % 4 == 0 -> in-range threads write full float4

    // Load A columns (SoA, coalesced float4) and pack as f32x2 pairs.
    u64 pa01[KA], pa23[KA];
#pragma unroll
    for (int k = 0; k < KA; k++) {
        float4 f = *(const float4*)(g_A + (size_t)k * NN + n0);
        pa01[k] = pack2(f.x, f.y);
        pa23[k] = pack2(f.z, f.w);
    }

    float* outBase = out + (size_t)mBase * NN + n0;
#pragma unroll 2
    for (int mi = 0; mi < MC; ++mi) {
        const ulonglong2* bb = (const ulonglong2*)(Bs + mi * KB);  // 6x LDS.128
        ulonglong2 b01 = bb[0];
        u64 acc01 = b01.x, acc23 = b01.x;   // init = c0*z0[m] in both lanes
        acc01 = fma2(pa01[0], b01.y, acc01);
        acc23 = fma2(pa23[0], b01.y, acc23);
#pragma unroll
        for (int kk = 1; kk < 6; kk++) {
            ulonglong2 b = bb[kk];          // B slots 2kk, 2kk+1 -> A rows 2kk-1, 2kk
            acc01 = fma2(pa01[2 * kk - 1], b.x, acc01);
            acc23 = fma2(pa23[2 * kk - 1], b.x, acc23);
            acc01 = fma2(pa01[2 * kk],     b.y, acc01);
            acc23 = fma2(pa23[2 * kk],     b.y, acc23);
        }
        float4 o;
        unpack2(acc01, o.x, o.y);
        unpack2(acc23, o.z, o.w);
        asm volatile("st.global.cs.v4.f32 [%0], {%1,%2,%3,%4};"
                     :: "l"(outBase + (size_t)mi * NN),
                        "f"(o.x), "f"(o.y), "f"(o.z), "f"(o.w) : "memory");
    }
}

extern "C" void kernel_launch(void* const* d_in, const int* in_sizes, int n_in,
                              void* d_out, int out_size) {
    // Input order: X, phi, POD_modes, c_coef, z_values, zsin, zcos,
    //              ztanh, sin_coef, cos_coef, tanh_coef, omega
    const float* phi   = (const float*)d_in[1];
    const float* POD   = (const float*)d_in[2];
    const float* c     = (const float*)d_in[3];
    const float* z     = (const float*)d_in[4];
    const float* zsin  = (const float*)d_in[5];
    const float* zcos  = (const float*)d_in[6];
    const float* ztanh = (const float*)d_in[7];
    const float* sc    = (const float*)d_in[8];
    const float* cc    = (const float*)d_in[9];
    const float* tc    = (const float*)d_in[10];
    const float* omega = (const float*)d_in[11];

    float* out        = (float*)d_out;
    float* out_final  = out;                              // (M, N)
    float* out_latent = out + (size_t)MM * NN;            // (N, 2)
    float* out_z      = out_latent + (size_t)NN * 2;      // (6, M)

    prep_A<<<(NN / 4 + TPB - 1) / TPB, TPB>>>(phi, POD, c, omega, out_latent);
    prep_B<<<(MM + 255) / 256, 256>>>(z, zsin, zcos, ztanh, sc, cc, tc, c, out_z);

    dim3 grid((NN + TPB * VN - 1) / (TPB * VN), MT);  // (196, 5) = 980 blocks
    main_kernel<<<grid, TPB>>>(out_final);
}

// round 4
// speedup vs baseline: 1.2629x; 1.2629x over previous
#include <cuda_runtime.h>

#define NN 100000
#define MM 1000
#define KA 11    // A rank terms (k=0 of original folded into B slot 0)
#define KB 12    // B per m: [0]=c0*z0 (acc init), [1..11] pair with A[0..10]
#define TPB 256
#define VN 4     // n per thread (float4 store)
#define MC 100   // m per block tile
#define MT 10    // m tiles (MC*MT = MM)

typedef unsigned long long u64;

__device__ __forceinline__ u64 pack2(float lo, float hi) {
    u64 r; asm("mov.b64 %0, {%1,%2};" : "=l"(r) : "f"(lo), "f"(hi)); return r;
}
__device__ __forceinline__ void unpack2(u64 v, float& lo, float& hi) {
    asm("mov.b64 {%0,%1}, %2;" : "=f"(lo), "=f"(hi) : "l"(v));
}
__device__ __forceinline__ u64 fma2(u64 a, u64 b, u64 c) {
    u64 d; asm("fma.rn.f32x2 %0, %1, %2, %3;" : "=l"(d) : "l"(a), "l"(b), "l"(c)); return d;
}
__device__ __forceinline__ float fast_sin(float x)  { float r; asm("sin.approx.f32 %0, %1;"  : "=f"(r) : "f"(x)); return r; }
__device__ __forceinline__ float fast_cos(float x)  { float r; asm("cos.approx.f32 %0, %1;"  : "=f"(r) : "f"(x)); return r; }
__device__ __forceinline__ float fast_tanh(float x) { float r; asm("tanh.approx.f32 %0, %1;" : "=f"(r) : "f"(x)); return r; }

// Single fused kernel: computes A features inline per n-range, B tile per m-range
// into shared, then streams the rank-12 outer product.
//   out[m*NN + n] = c0*z0[m] + sum_{k=0..10} A[n,k] * B[m,k+1]
__global__ void __launch_bounds__(TPB)
fused_kernel(const float* __restrict__ phi, const float* __restrict__ POD,
             const float* __restrict__ c, const float* __restrict__ omega,
             const float* __restrict__ z, const float* __restrict__ zsin,
             const float* __restrict__ zcos, const float* __restrict__ ztanh,
             const float* __restrict__ sc, const float* __restrict__ cc,
             const float* __restrict__ tc,
             float* __restrict__ out_final, float* __restrict__ out_latent,
             float* __restrict__ out_z) {
    __shared__ __align__(16) u64 Bs[MC * KB];  // B rows, value duplicated in both lanes

    const int tid = threadIdx.x;
    const int mBase = blockIdx.y * MC;

    // ---- B tile: threads 0..MC-1 compute one m row each (tiny, L2-resident src) ----
    if (tid < MC) {
        int m = mBase + tid;
        u64* b = Bs + tid * KB;
        b[0] = pack2(c[0] * z[m], c[0] * z[m]);
#pragma unroll
        for (int t = 1; t < 6; t++) {
            float v = z[t * MM + m];
            b[t] = pack2(v, v);
        }
        float v6  = sc[0] * zsin[m];        b[6]  = pack2(v6, v6);
        float v7  = sc[1] * zsin[MM + m];   b[7]  = pack2(v7, v7);
        float v8  = cc[0] * zcos[m];        b[8]  = pack2(v8, v8);
        float v9  = cc[1] * zcos[MM + m];   b[9]  = pack2(v9, v9);
        float v10 = tc[0] * ztanh[m];       b[10] = pack2(v10, v10);
        float v11 = tc[1] * ztanh[MM + m];  b[11] = pack2(v11, v11);
    }

    // ---- z_values copy (once, by block (0,0)) ----
    if (blockIdx.x == 0 && blockIdx.y == 0) {
        for (int i = tid; i < 6 * MM; i += TPB) out_z[i] = z[i];
    }
    __syncthreads();

    const int n0 = (blockIdx.x * TPB + tid) * VN;
    if (n0 >= NN) return;  // NN % 4 == 0; in-range threads always full float4

    // ---- A features inline for this thread's 4 n's ----
    float4 p0 = *(const float4*)(phi + n0);
    float4 p1 = *(const float4*)(phi + NN + n0);
    float4 qa = *(const float4*)(POD + 2 * n0);
    float4 qb = *(const float4*)(POD + 2 * n0 + 4);

    float y0[4], y1[4];
    y0[0] = p0.x * qa.x;  y1[0] = p1.x * qa.y;
    y0[1] = p0.y * qa.z;  y1[1] = p1.y * qa.w;
    y0[2] = p0.z * qb.x;  y1[2] = p1.z * qb.y;
    y0[3] = p0.w * qb.z;  y1[3] = p1.w * qb.w;

    if (blockIdx.y == 0) {  // latent_spatial (N,2): [y0, y1] interleaved
        *(float4*)(out_latent + 2 * n0)     = make_float4(y0[0], y1[0], y0[1], y1[1]);
        *(float4*)(out_latent + 2 * n0 + 4) = make_float4(y0[2], y1[2], y0[3], y1[3]);
    }

    float c1 = c[1], c2 = c[2], c3 = c[3], c4 = c[4], c5 = c[5];
    float w0 = omega[0], w1 = omega[1], w2 = omega[2];
    float w3 = omega[3], w4 = omega[4], w5 = omega[5];

    float a[4][KA];
#pragma unroll
    for (int j = 0; j < 4; j++) {
        a[j][0]  = c1 * y0[j];
        a[j][1]  = c2 * y1[j];
        a[j][2]  = c3 * y0[j] * y0[j];
        a[j][3]  = c4 * y0[j] * y1[j];
        a[j][4]  = c5 * y1[j] * y1[j];
        a[j][5]  = fast_sin(w0 * y0[j]);
        a[j][6]  = fast_sin(w3 * y1[j]);
        a[j][7]  = fast_cos(w1 * y0[j]);
        a[j][8]  = fast_cos(w4 * y1[j]);
        a[j][9]  = fast_tanh(w2 * y0[j]);
        a[j][10] = fast_tanh(w5 * y1[j]);
    }
    u64 pa01[KA], pa23[KA];
#pragma unroll
    for (int k = 0; k < KA; k++) {
        pa01[k] = pack2(a[0][k], a[1][k]);
        pa23[k] = pack2(a[2][k], a[3][k]);
    }

    // ---- main store stream ----
    float* outBase = out_final + (size_t)mBase * NN + n0;
#pragma unroll 2
    for (int mi = 0; mi < MC; ++mi) {
        const ulonglong2* bb = (const ulonglong2*)(Bs + mi * KB);  // 6x LDS.128
        ulonglong2 b01 = bb[0];
        u64 acc01 = b01.x, acc23 = b01.x;   // init = c0*z0[m]
        acc01 = fma2(pa01[0], b01.y, acc01);
        acc23 = fma2(pa23[0], b01.y, acc23);
#pragma unroll
        for (int kk = 1; kk < 6; kk++) {
            ulonglong2 b = bb[kk];          // B slots 2kk, 2kk+1 -> A rows 2kk-1, 2kk
            acc01 = fma2(pa01[2 * kk - 1], b.x, acc01);
            acc23 = fma2(pa23[2 * kk - 1], b.x, acc23);
            acc01 = fma2(pa01[2 * kk],     b.y, acc01);
            acc23 = fma2(pa23[2 * kk],     b.y, acc23);
        }
        float4 o;
        unpack2(acc01, o.x, o.y);
        unpack2(acc23, o.z, o.w);
        asm volatile("st.global.cs.v4.f32 [%0], {%1,%2,%3,%4};"
                     :: "l"(outBase + (size_t)mi * NN),
                        "f"(o.x), "f"(o.y), "f"(o.z), "f"(o.w) : "memory");
    }
}

extern "C" void kernel_launch(void* const* d_in, const int* in_sizes, int n_in,
                              void* d_out, int out_size) {
    // Input order: X, phi, POD_modes, c_coef, z_values, zsin, zcos,
    //              ztanh, sin_coef, cos_coef, tanh_coef, omega
    const float* phi   = (const float*)d_in[1];
    const float* POD   = (const float*)d_in[2];
    const float* c     = (const float*)d_in[3];
    const float* z     = (const float*)d_in[4];
    const float* zsin  = (const float*)d_in[5];
    const float* zcos  = (const float*)d_in[6];
    const float* ztanh = (const float*)d_in[7];
    const float* sc    = (const float*)d_in[8];
    const float* cc    = (const float*)d_in[9];
    const float* tc    = (const float*)d_in[10];
    const float* omega = (const float*)d_in[11];

    float* out        = (float*)d_out;
    float* out_final  = out;                              // (M, N)
    float* out_latent = out + (size_t)MM * NN;            // (N, 2)
    float* out_z      = out_latent + (size_t)NN * 2;      // (6, M)

    dim3 grid((NN + TPB * VN - 1) / (TPB * VN), MT);      // (98, 10) = 980 blocks
    fused_kernel<<<grid, TPB>>>(phi, POD, c, omega, z, zsin, zcos, ztanh,
                                sc, cc, tc, out_final, out_latent, out_z);
}